// round 1
// baseline (speedup 1.0000x reference)
#include <cuda_runtime.h>
#include <cuda_bf16.h>
#include <math.h>

// Problem constants (fixed shapes from reference):
// B=2, G=8 -> BG=16 ; N=4096 ; D=1024 ; H=16, Dh=64 (H/Dh unused after collapse)
#define BG   16
#define NSEQ 4096
#define DIM  1024
#define NROWS (BG * NSEQ)      // 65536 rows of length 1024
#define EPSF 1e-6f

// Scratch (no cudaMalloc allowed): v = guidance @ Wv^T + bv ; o = v @ Wout^T + bo
__device__ float g_v[BG * DIM];
__device__ float g_o[BG * DIM];

// ---------------------------------------------------------------------------
// GEMV: out[bg, i] = sum_d A[bg, d] * W[i, d] + bias[i]
// One warp per output element (16 * 1024 = 16384 warps).
// A rows (16 x 4KB) and W (4MB) are L2-resident -> compute/latency trivial.
// ---------------------------------------------------------------------------
__global__ void gemv16_kernel(const float* __restrict__ A,     // [BG, DIM]
                              const float* __restrict__ W,     // [DIM, DIM] row-major
                              const float* __restrict__ bias,  // [DIM]
                              float* __restrict__ out)         // [BG, DIM]
{
    const int gw   = (blockIdx.x * blockDim.x + threadIdx.x) >> 5;
    const int lane = threadIdx.x & 31;
    if (gw >= BG * DIM) return;
    const int bg = gw >> 10;        // / DIM
    const int i  = gw & (DIM - 1);  // % DIM

    const float* __restrict__ a = A + bg * DIM;
    const float* __restrict__ w = W + (size_t)i * DIM;

    float s = 0.0f;
    // 1024 elems / 32 lanes = 32 per lane = 8 float4 per lane
    #pragma unroll
    for (int d = lane * 4; d < DIM; d += 32 * 4) {
        float4 av = *reinterpret_cast<const float4*>(a + d);
        float4 wv = *reinterpret_cast<const float4*>(w + d);
        s = fmaf(av.x, wv.x, s);
        s = fmaf(av.y, wv.y, s);
        s = fmaf(av.z, wv.z, s);
        s = fmaf(av.w, wv.w, s);
    }
    #pragma unroll
    for (int off = 16; off > 0; off >>= 1)
        s += __shfl_xor_sync(0xffffffffu, s, off);

    if (lane == 0) out[gw] = s + bias[i];
}

// ---------------------------------------------------------------------------
// Fused residual-add + RMSNorm over rows of length 1024.
// One 256-thread block per row; one float4 per thread.
// y[row, :] = (x[row,:] + o[bg,:]) * rsqrt(mean((x+o)^2) + eps) * norm_w
// HBM traffic: 256MB read (x) + 256MB write (y); o and norm_w are L2 hits.
// ---------------------------------------------------------------------------
__global__ void __launch_bounds__(256)
fused_add_rmsnorm_kernel(const float* __restrict__ x,   // [NROWS, DIM]
                         const float* __restrict__ o,   // [BG, DIM]
                         const float* __restrict__ w,   // [DIM]
                         float* __restrict__ y)         // [NROWS, DIM]
{
    const int row = blockIdx.x;              // 0 .. 65535
    const int bg  = row >> 12;               // row / 4096
    const int t   = threadIdx.x;             // 0 .. 255
    const size_t base = (size_t)row * DIM + t * 4;

    const float4 x4 = *reinterpret_cast<const float4*>(x + base);
    const float4 o4 = *reinterpret_cast<const float4*>(o + bg * DIM + t * 4);

    float4 s;
    s.x = x4.x + o4.x;
    s.y = x4.y + o4.y;
    s.z = x4.z + o4.z;
    s.w = x4.w + o4.w;

    float ss = s.x * s.x + s.y * s.y + s.z * s.z + s.w * s.w;

    // warp reduce
    #pragma unroll
    for (int off = 16; off > 0; off >>= 1)
        ss += __shfl_xor_sync(0xffffffffu, ss, off);

    __shared__ float red[8];
    __shared__ float inv_s;
    const int lane = t & 31;
    const int wid  = t >> 5;
    if (lane == 0) red[wid] = ss;
    __syncthreads();
    if (wid == 0) {
        float v = (lane < 8) ? red[lane] : 0.0f;
        #pragma unroll
        for (int off = 4; off > 0; off >>= 1)
            v += __shfl_xor_sync(0xffffffffu, v, off);
        if (lane == 0)
            inv_s = rsqrtf(v * (1.0f / (float)DIM) + EPSF);
    }
    __syncthreads();
    const float inv = inv_s;

    const float4 w4 = *reinterpret_cast<const float4*>(w + t * 4);
    float4 r;
    r.x = s.x * inv * w4.x;
    r.y = s.y * inv * w4.y;
    r.z = s.z * inv * w4.z;
    r.w = s.w * inv * w4.w;
    *reinterpret_cast<float4*>(y + base) = r;
}

// ---------------------------------------------------------------------------
// Launch
// Inputs (metadata order):
//  0: x          [2,8,4096,1024] f32
//  1: guidance   [2,8,1024]      f32
//  2: in_proj_w  [3072,1024]     f32   (Wq|Wk|Wv stacked; Wv = rows 2048..3071)
//  3: in_proj_b  [3072]          f32
//  4: out_proj_w [1024,1024]     f32
//  5: out_proj_b [1024]          f32
//  6: norm_w     [1024]          f32
// Output: y [2,8,4096,1024] f32
// ---------------------------------------------------------------------------
extern "C" void kernel_launch(void* const* d_in, const int* in_sizes, int n_in,
                              void* d_out, int out_size)
{
    const float* x        = (const float*)d_in[0];
    const float* guidance = (const float*)d_in[1];
    const float* in_w     = (const float*)d_in[2];
    const float* in_b     = (const float*)d_in[3];
    const float* out_w    = (const float*)d_in[4];
    const float* out_b    = (const float*)d_in[5];
    const float* norm_w   = (const float*)d_in[6];
    float* y = (float*)d_out;

    float* v_scratch;
    float* o_scratch;
    cudaGetSymbolAddress((void**)&v_scratch, g_v);
    cudaGetSymbolAddress((void**)&o_scratch, g_o);

    const float* Wv = in_w + (size_t)2 * DIM * DIM;  // rows [2048:3072]
    const float* bv = in_b + 2 * DIM;

    // 16384 warps -> 2048 blocks of 256 threads
    const int gemv_blocks = (BG * DIM * 32) / 256;
    gemv16_kernel<<<gemv_blocks, 256>>>(guidance, Wv, bv, v_scratch);
    gemv16_kernel<<<gemv_blocks, 256>>>(v_scratch, out_w, out_b, o_scratch);

    fused_add_rmsnorm_kernel<<<NROWS, 256>>>(x, o_scratch, norm_w, y);
}

// round 2
// speedup vs baseline: 1.0009x; 1.0009x over previous
#include <cuda_runtime.h>
#include <cuda_bf16.h>
#include <math.h>

// Problem constants (fixed shapes from reference):
// B=2, G=8 -> BG=16 ; N=4096 ; D=1024 ; H=16, Dh=64 (H/Dh unused after collapse)
#define BG   16
#define NSEQ 4096
#define DIM  1024
#define NROWS (BG * NSEQ)      // 65536 rows of length 1024
#define EPSF 1e-6f

// Scratch (no cudaMalloc allowed): v = guidance @ Wv^T + bv ; o = v @ Wout^T + bo
__device__ float g_v[BG * DIM];
__device__ float g_o[BG * DIM];

// ---------------------------------------------------------------------------
// GEMV: out[bg, i] = sum_d A[bg, d] * W[i, d] + bias[i]
// One warp per output element (16 * 1024 = 16384 warps).
// A rows (16 x 4KB) and W (4MB) are L2-resident -> compute/latency trivial.
// ---------------------------------------------------------------------------
__global__ void gemv16_kernel(const float* __restrict__ A,     // [BG, DIM]
                              const float* __restrict__ W,     // [DIM, DIM] row-major
                              const float* __restrict__ bias,  // [DIM]
                              float* __restrict__ out)         // [BG, DIM]
{
    const int gw   = (blockIdx.x * blockDim.x + threadIdx.x) >> 5;
    const int lane = threadIdx.x & 31;
    if (gw >= BG * DIM) return;
    const int bg = gw >> 10;        // / DIM
    const int i  = gw & (DIM - 1);  // % DIM

    const float* __restrict__ a = A + bg * DIM;
    const float* __restrict__ w = W + (size_t)i * DIM;

    float s = 0.0f;
    // 1024 elems / 32 lanes = 32 per lane = 8 float4 per lane
    #pragma unroll
    for (int d = lane * 4; d < DIM; d += 32 * 4) {
        float4 av = *reinterpret_cast<const float4*>(a + d);
        float4 wv = *reinterpret_cast<const float4*>(w + d);
        s = fmaf(av.x, wv.x, s);
        s = fmaf(av.y, wv.y, s);
        s = fmaf(av.z, wv.z, s);
        s = fmaf(av.w, wv.w, s);
    }
    #pragma unroll
    for (int off = 16; off > 0; off >>= 1)
        s += __shfl_xor_sync(0xffffffffu, s, off);

    if (lane == 0) out[gw] = s + bias[i];
}

// ---------------------------------------------------------------------------
// Fused residual-add + RMSNorm over rows of length 1024.
// One 256-thread block per row; one float4 per thread.
// y[row, :] = (x[row,:] + o[bg,:]) * rsqrt(mean((x+o)^2) + eps) * norm_w
// HBM traffic: 256MB read (x) + 256MB write (y); o and norm_w are L2 hits.
// ---------------------------------------------------------------------------
__global__ void __launch_bounds__(256)
fused_add_rmsnorm_kernel(const float* __restrict__ x,   // [NROWS, DIM]
                         const float* __restrict__ o,   // [BG, DIM]
                         const float* __restrict__ w,   // [DIM]
                         float* __restrict__ y)         // [NROWS, DIM]
{
    const int row = blockIdx.x;              // 0 .. 65535
    const int bg  = row >> 12;               // row / 4096
    const int t   = threadIdx.x;             // 0 .. 255
    const size_t base = (size_t)row * DIM + t * 4;

    const float4 x4 = *reinterpret_cast<const float4*>(x + base);
    const float4 o4 = *reinterpret_cast<const float4*>(o + bg * DIM + t * 4);

    float4 s;
    s.x = x4.x + o4.x;
    s.y = x4.y + o4.y;
    s.z = x4.z + o4.z;
    s.w = x4.w + o4.w;

    float ss = s.x * s.x + s.y * s.y + s.z * s.z + s.w * s.w;

    // warp reduce
    #pragma unroll
    for (int off = 16; off > 0; off >>= 1)
        ss += __shfl_xor_sync(0xffffffffu, ss, off);

    __shared__ float red[8];
    __shared__ float inv_s;
    const int lane = t & 31;
    const int wid  = t >> 5;
    if (lane == 0) red[wid] = ss;
    __syncthreads();
    if (wid == 0) {
        float v = (lane < 8) ? red[lane] : 0.0f;
        #pragma unroll
        for (int off = 4; off > 0; off >>= 1)
            v += __shfl_xor_sync(0xffffffffu, v, off);
        if (lane == 0)
            inv_s = rsqrtf(v * (1.0f / (float)DIM) + EPSF);
    }
    __syncthreads();
    const float inv = inv_s;

    const float4 w4 = *reinterpret_cast<const float4*>(w + t * 4);
    float4 r;
    r.x = s.x * inv * w4.x;
    r.y = s.y * inv * w4.y;
    r.z = s.z * inv * w4.z;
    r.w = s.w * inv * w4.w;
    *reinterpret_cast<float4*>(y + base) = r;
}

// ---------------------------------------------------------------------------
// Launch
// Inputs (metadata order):
//  0: x          [2,8,4096,1024] f32
//  1: guidance   [2,8,1024]      f32
//  2: in_proj_w  [3072,1024]     f32   (Wq|Wk|Wv stacked; Wv = rows 2048..3071)
//  3: in_proj_b  [3072]          f32
//  4: out_proj_w [1024,1024]     f32
//  5: out_proj_b [1024]          f32
//  6: norm_w     [1024]          f32
// Output: y [2,8,4096,1024] f32
// ---------------------------------------------------------------------------
extern "C" void kernel_launch(void* const* d_in, const int* in_sizes, int n_in,
                              void* d_out, int out_size)
{
    const float* x        = (const float*)d_in[0];
    const float* guidance = (const float*)d_in[1];
    const float* in_w     = (const float*)d_in[2];
    const float* in_b     = (const float*)d_in[3];
    const float* out_w    = (const float*)d_in[4];
    const float* out_b    = (const float*)d_in[5];
    const float* norm_w   = (const float*)d_in[6];
    float* y = (float*)d_out;

    float* v_scratch;
    float* o_scratch;
    cudaGetSymbolAddress((void**)&v_scratch, g_v);
    cudaGetSymbolAddress((void**)&o_scratch, g_o);

    const float* Wv = in_w + (size_t)2 * DIM * DIM;  // rows [2048:3072]
    const float* bv = in_b + 2 * DIM;

    // 16384 warps -> 2048 blocks of 256 threads
    const int gemv_blocks = (BG * DIM * 32) / 256;
    gemv16_kernel<<<gemv_blocks, 256>>>(guidance, Wv, bv, v_scratch);
    gemv16_kernel<<<gemv_blocks, 256>>>(v_scratch, out_w, out_b, o_scratch);

    fused_add_rmsnorm_kernel<<<NROWS, 256>>>(x, o_scratch, norm_w, y);
}